// round 15
// baseline (speedup 1.0000x reference)
#include <cuda_runtime.h>
#include <cstdint>

// Problem constants (fixed by the reference).
#define C_OUT   96
#define NK      11
#define C_IN    1056
#define GB      8
#define NTILES  (C_OUT*GB)         // 768 tiles, one per (b, c_out)
#define HOUT    56
#define WOUT    56
#define HIN     60
#define EP      2
#define PLANE   3600
#define PLANE_BYTES 14400
#define NPIX    3136
#define NCW     21                 // compute warps: 14 h-role + 7 v-role
#define NHW     14                 // h-role warps (448 threads)
#define THREADS (NCW*32 + 32)      // 704: 21 compute warps + 1 producer warp
#define NCTA    296                // 2 CTAs per SM
#define OUT_PLANE ((size_t)GB*C_OUT*NPIX)

// h/id mapping: 64 threads (2 warps) per row chunk (7 chunks), h = h0h + 7k, k = 0..7
#define KROWS_H 7
#define RSTEP_H (KROWS_H*HIN)      // 420
// v mapping: 1 warp per row chunk (7 chunks, 28 active lanes x 2 w), h = h0v + 7k, k = 0..7
#define KROWS_V 7
#define RSTEP_V (KROWS_V*HIN)      // 420

// 5-slot plane ring with shared inter-slot zero guards -> ~111 KB smem,
// 2 CTAs per SM (44 warps) for latency hiding. 1408 threads -> 46 regs/thread;
// role-split keeps each warp's accumulator set small enough to avoid spills.
// All OOB offsets stay within [-1618, +4747] of a plane start; 1620-float
// guards (shared between adjacent slots) absorb them.
#define NSLOT       5
#define GUARD       1620
#define SLOT_STRIDE (PLANE + GUARD)                 // 5220
#define SM_DATA     (NSLOT*SLOT_STRIDE + GUARD)     // 27720 floats
#define OFF_TAB     SM_DATA                          // 2 x 44 float4 (double buffer)
#define OFF_WID     (OFF_TAB + 352)                  // 2 x 12 floats
#define OFF_Q       (OFF_WID + 24)                   // 4 ints (tile queue)
#define OFF_BAR     (OFF_Q + 4)                      // 5 full + 5 empty u64
#define SMEM_FLOATS (OFF_BAR + 20)
#define SMEM_BYTES  (SMEM_FLOATS * 4)                // ~111 KB

__device__ int g_tile_ctr;
__global__ void reset_kernel() { g_tile_ctr = 0; }

__device__ __forceinline__ uint32_t smem_u32(const void* p) {
    uint32_t a;
    asm("{ .reg .u64 t; cvta.to.shared.u64 t, %1; cvt.u32.u64 %0, t; }"
        : "=r"(a) : "l"(p));
    return a;
}
__device__ __forceinline__ void mbar_init(uint32_t mbar, uint32_t cnt) {
    asm volatile("mbarrier.init.shared.b64 [%0], %1;" :: "r"(mbar), "r"(cnt) : "memory");
}
__device__ __forceinline__ void mbar_wait(uint32_t mbar, int parity) {
    asm volatile(
        "{\n\t.reg .pred P;\n"
        "W_%=:\n\t"
        "mbarrier.try_wait.parity.acquire.cta.shared::cta.b64 P, [%0], %1, 0x989680;\n\t"
        "@P bra D_%=;\n\t"
        "bra W_%=;\n"
        "D_%=:\n\t}"
        :: "r"(mbar), "r"(parity) : "memory");
}

__global__ __launch_bounds__(THREADS, 2)
void addshift_kernel(const float* __restrict__ x,
                     const float* __restrict__ w1,
                     const float* __restrict__ w2,
                     const float* __restrict__ w3,
                     const int*   __restrict__ pad_hv,
                     const int*   __restrict__ idx_identit,
                     float* __restrict__ out)
{
    extern __shared__ float smem[];
    float4* tab = (float4*)(smem + OFF_TAB);   // [2][44]
    float*  wid = smem + OFF_WID;              // [2][12]
    int*    q   = (int*)(smem + OFF_Q);

    const int tid = threadIdx.x;
    const uint32_t smem_base = smem_u32(smem);
    const uint32_t fbar0 = smem_base + (uint32_t)OFF_BAR * 4u;        // full[s]
    const uint32_t ebar0 = fbar0 + 8u * NSLOT;                        // empty[s]

    // Zero data region once (guards stay zero; plane bytes overwritten by TMA).
    {
        float4* d = (float4*)smem;
        const float4 z = make_float4(0.f, 0.f, 0.f, 0.f);
        for (int i = tid; i < SM_DATA / 4; i += THREADS) d[i] = z;
    }
    if (tid == 0) {
        for (int s = 0; s < NSLOT; s++) {
            mbar_init(fbar0 + 8u * s, 1);
            mbar_init(ebar0 + 8u * s, NCW);
        }
    }
    __syncthreads();   // the only full-CTA barrier

    // ================= producer warp =================
    if (tid >= NCW * 32) {
        if (tid == NCW * 32) {
            asm volatile("fence.proxy.async.shared::cta;" ::: "memory");
            int pnk = 0, ptq = 0;
            for (int p = 0;; p++) {
                int s = p % NSLOT;
                if (p >= NSLOT)
                    mbar_wait(ebar0 + 8u * s, ((p - NSLOT) / NSLOT) & 1);
                if (pnk == 0) {
                    int t = atomicAdd(&g_tile_ctr, 1);
                    q[ptq & 3] = (t < NTILES) ? t : -1;
                }
                int t = q[ptq & 3];
                uint32_t bar = fbar0 + 8u * s;
                if (t < 0) {  // sentinel: flip full[s] so consumers see q=-1 and exit
                    asm volatile("mbarrier.arrive.shared.b64 _, [%0];" :: "r"(bar) : "memory");
                    break;
                }
                uint32_t dst = smem_base + (uint32_t)(GUARD + s * SLOT_STRIDE) * 4u;
                const float* src = x + (size_t)((t / C_OUT) * C_IN + (t % C_OUT) * NK + pnk) * PLANE;
                asm volatile("mbarrier.arrive.expect_tx.shared.b64 _, [%0], %1;"
                             :: "r"(bar), "r"((uint32_t)PLANE_BYTES) : "memory");
                asm volatile("cp.async.bulk.shared::cta.global.mbarrier::complete_tx::bytes "
                             "[%0], [%1], %2, [%3];"
                             :: "r"(dst), "l"(src), "r"((uint32_t)PLANE_BYTES), "r"(bar) : "memory");
                if (++pnk == NK) { pnk = 0; ptq++; }
            }
        }
        return;
    }

    // ================= compute warps =================
    const bool is_h = (tid < NHW * 32);
    const bool lane0 = ((tid & 31) == 0);

    // h/id mapping (scalar, row-pure): 64 threads per row chunk, 7 chunks.
    const int lh   = tid & 63;
    const int h0h  = tid >> 6;            // 0..6 (h-role only)
    const int colh = lh + EP;
    const int rb0h = (h0h + EP) * HIN;
    const bool act_h = (lh < WOUT);
    // v mapping (2-wide float2, row-pure): 1 warp per row chunk, 7 chunks.
    const int vt   = tid - NHW * 32;      // 0..223 (v-role only)
    const int l2   = vt & 31;
    const int h0v  = vt >> 5;             // 0..6
    const int col0 = 2*l2 + EP;           // even -> LDS.64 aligned
    const int vrow0 = h0v + EP;
    const bool act_v = (l2 < 28);

    int p = 0, tq = 0;
    for (;;) {
        mbar_wait(fbar0 + 8u * (p % NSLOT), (p / NSLOT) & 1);   // plane 0 ready; q visible
        const int t = q[tq & 3];
        if (t < 0) break;
        const int co = t % C_OUT, b = t / C_OUT, c0 = co * NK;

        // Double-buffered term tables for this tile.
        float4* tb = tab + (tq & 1) * 44;
        float*  wb = wid + (tq & 1) * 12;
        if (tid < 44) {
            int nk = tid >> 2, g = tid & 3, c = c0 + nk;
            float4 e;
            e.x = __int_as_float(pad_hv[c*8 + g]);
            e.y = w1[g*C_IN + c];
            e.z = __int_as_float(pad_hv[c*8 + 4 + g]);
            e.w = w2[g*C_IN + c];
            tb[tid] = e;
        }
        if (tid >= 64 && tid < 64 + NK) {
            int nk = tid - 64;
            float sw = 0.f;
            #pragma unroll
            for (int g = 0; g < 4; g++)
                if (idx_identit[co*4 + g] - c0 == nk) sw += w3[g*C_OUT + co];
            wb[nk] = sw;
        }
        asm volatile("bar.sync 1, %0;" :: "n"(NCW*32) : "memory");  // tables ready

        const size_t tbase = ((size_t)(b * C_OUT + co)) * NPIX;

        if (is_h) {
            // ---------- h role: h shifts + identity (scalar, row-pure) ----------
            float acc_h[8] = {0.f,0.f,0.f,0.f,0.f,0.f,0.f,0.f};
            float acc_i[8] = {0.f,0.f,0.f,0.f,0.f,0.f,0.f,0.f};

            for (int nk = 0; nk < NK; nk++) {
                int s = p % NSLOT;
                if (nk) mbar_wait(fbar0 + 8u * s, (p / NSLOT) & 1);
                const float* bh = smem + GUARD + s * SLOT_STRIDE + rb0h;

                #pragma unroll
                for (int g = 0; g < 4; g++) {
                    float4 e = tb[nk*4 + g];
                    int   sh = __float_as_int(e.x);
                    float wh = e.y;
                    int iw = colh + sh;
                    float wt = ((unsigned)iw < (unsigned)HIN) ? wh : 0.0f;
                    const float* ph = bh + iw;
                    #pragma unroll
                    for (int k = 0; k < 8; k++)
                        acc_h[k] = fmaf(ph[k*RSTEP_H], wt, acc_h[k]);
                }
                float wi = wb[nk];
                if (wi != 0.0f) {      // warp-uniform branch
                    const float* pi = bh + colh;
                    #pragma unroll
                    for (int k = 0; k < 8; k++)
                        acc_i[k] = fmaf(pi[k*RSTEP_H], wi, acc_i[k]);
                }
                if (lane0) {
                    asm volatile("mbarrier.arrive.release.cta.shared::cta.b64 _, [%0];"
                        :: "r"(ebar0 + 8u * s),
                           "f"(acc_h[0]), "f"(acc_h[1]), "f"(acc_h[2]), "f"(acc_h[3]),
                           "f"(acc_h[4]), "f"(acc_h[5]), "f"(acc_h[6]), "f"(acc_h[7]),
                           "f"(acc_i[0]), "f"(acc_i[3]), "f"(acc_i[5]), "f"(acc_i[7])
                        : "memory");
                }
                p++;
            }
            if (act_h) {
                float* oh = out;
                float* oi = out + 2*OUT_PLANE;
                const size_t ob = tbase + (size_t)h0h * WOUT + lh;
                #pragma unroll
                for (int k = 0; k < 8; k++) {
                    oh[ob + (size_t)(KROWS_H * k) * WOUT] = acc_h[k];
                    oi[ob + (size_t)(KROWS_H * k) * WOUT] = acc_i[k];
                }
            }
        } else {
            // ---------- v role: vertical shifts (float2, row-pure) ----------
            float2 acc_v[8] = {{0.f,0.f},{0.f,0.f},{0.f,0.f},{0.f,0.f},
                               {0.f,0.f},{0.f,0.f},{0.f,0.f},{0.f,0.f}};

            for (int nk = 0; nk < NK; nk++) {
                int s = p % NSLOT;
                if (nk) mbar_wait(fbar0 + 8u * s, (p / NSLOT) & 1);
                const float* bv = smem + GUARD + s * SLOT_STRIDE + col0;

                #pragma unroll
                for (int g = 0; g < 4; g++) {
                    float4 e = tb[nk*4 + g];
                    int   sv = __float_as_int(e.z);
                    float wv = e.w;
                    const float* pv = bv + (vrow0 + sv) * HIN;
                    #pragma unroll
                    for (int k = 0; k < 8; k++) {
                        float2 a = *(const float2*)(pv + k*RSTEP_V);
                        acc_v[k].x = fmaf(a.x, wv, acc_v[k].x);
                        acc_v[k].y = fmaf(a.y, wv, acc_v[k].y);
                    }
                }
                if (lane0) {
                    asm volatile("mbarrier.arrive.release.cta.shared::cta.b64 _, [%0];"
                        :: "r"(ebar0 + 8u * s),
                           "f"(acc_v[0].x), "f"(acc_v[1].y), "f"(acc_v[2].x), "f"(acc_v[3].y),
                           "f"(acc_v[4].x), "f"(acc_v[5].y), "f"(acc_v[6].x), "f"(acc_v[7].y)
                        : "memory");
                }
                p++;
            }
            if (act_v) {
                float* ov = out + OUT_PLANE;
                const size_t ob = tbase + (size_t)h0v * WOUT + 2*l2;
                #pragma unroll
                for (int k = 0; k < 8; k++)
                    *(float2*)(ov + ob + (size_t)(KROWS_V * k) * WOUT) = acc_v[k];
            }
        }
        tq++;
    }
}

extern "C" void kernel_launch(void* const* d_in, const int* in_sizes, int n_in,
                              void* d_out, int out_size)
{
    const float* x           = (const float*)d_in[0];
    const float* w1          = (const float*)d_in[1];
    const float* w2          = (const float*)d_in[2];
    const float* w3          = (const float*)d_in[3];
    const int*   pad_hv      = (const int*)  d_in[4];
    const int*   idx_identit = (const int*)  d_in[5];
    float*       out         = (float*)d_out;

    cudaFuncSetAttribute(addshift_kernel,
                         cudaFuncAttributeMaxDynamicSharedMemorySize, SMEM_BYTES);

    reset_kernel<<<1, 32>>>();
    addshift_kernel<<<NCTA, THREADS, SMEM_BYTES>>>(x, w1, w2, w3, pad_hv,
                                                   idx_identit, out);
}

// round 16
// speedup vs baseline: 1.1223x; 1.1223x over previous
#include <cuda_runtime.h>
#include <cstdint>

// Problem constants (fixed by the reference).
#define C_OUT   96
#define NK      11
#define C_IN    1056
#define GB      8
#define NTILES  (C_OUT*GB)         // 768 tiles, one per (b, c_out)
#define HOUT    56
#define WOUT    56
#define HIN     60
#define EP      2
#define PLANE   3600
#define PLANE_BYTES 14400
#define NPIX    3136
#define NCW     14                 // compute warps per CTA
#define THREADS (NCW*32 + 32)      // 480: 14 compute warps + 1 producer warp
#define NCTA    296                // 2 CTAs per SM
#define OUT_PLANE ((size_t)GB*C_OUT*NPIX)

// h mapping: 64 threads (2 warps) per row chunk (7 chunks), h = h0h + 7k, k = 0..7
#define KROWS_H 7
#define RSTEP_H (KROWS_H*HIN)      // 420
// v/id mapping: 1 warp per row chunk (14 chunks, 28 active lanes x 2 w), h = h0v + 14k, k = 0..3
#define KROWS_V 14
#define RSTEP_V (KROWS_V*HIN)      // 840

// 5-slot plane ring with shared inter-slot zero guards -> ~111 KB smem,
// 2 CTAs per SM. All OOB offsets stay within [-1618, +4747] of a plane
// start; 1620-float guards (shared between adjacent slots) absorb them.
#define NSLOT       5
#define GUARD       1620
#define SLOT_STRIDE (PLANE + GUARD)                 // 5220
#define SM_DATA     (NSLOT*SLOT_STRIDE + GUARD)     // 27720 floats
#define OFF_TAB     SM_DATA                          // 2 x 44 float4 (double buffer)
#define OFF_WID     (OFF_TAB + 352)                  // 2 x 12 floats
#define OFF_Q       (OFF_WID + 24)                   // 4 ints (tile queue)
#define OFF_BAR     (OFF_Q + 4)                      // 5 full + 5 empty u64
#define SMEM_FLOATS (OFF_BAR + 20)
#define SMEM_BYTES  (SMEM_FLOATS * 4)                // ~111 KB

__device__ int g_tile_ctr;
__global__ void reset_kernel() { g_tile_ctr = 0; }

__device__ __forceinline__ uint32_t smem_u32(const void* p) {
    uint32_t a;
    asm("{ .reg .u64 t; cvta.to.shared.u64 t, %1; cvt.u32.u64 %0, t; }"
        : "=r"(a) : "l"(p));
    return a;
}
__device__ __forceinline__ void mbar_init(uint32_t mbar, uint32_t cnt) {
    asm volatile("mbarrier.init.shared.b64 [%0], %1;" :: "r"(mbar), "r"(cnt) : "memory");
}
__device__ __forceinline__ void mbar_wait(uint32_t mbar, int parity) {
    asm volatile(
        "{\n\t.reg .pred P;\n"
        "W_%=:\n\t"
        "mbarrier.try_wait.parity.acquire.cta.shared::cta.b64 P, [%0], %1, 0x989680;\n\t"
        "@P bra D_%=;\n\t"
        "bra W_%=;\n"
        "D_%=:\n\t}"
        :: "r"(mbar), "r"(parity) : "memory");
}

__global__ __launch_bounds__(THREADS, 2)
void addshift_kernel(const float* __restrict__ x,
                     const float* __restrict__ w1,
                     const float* __restrict__ w2,
                     const float* __restrict__ w3,
                     const int*   __restrict__ pad_hv,
                     const int*   __restrict__ idx_identit,
                     float* __restrict__ out)
{
    extern __shared__ float smem[];
    float4* tab = (float4*)(smem + OFF_TAB);   // [2][44]
    float*  wid = smem + OFF_WID;              // [2][12]
    int*    q   = (int*)(smem + OFF_Q);

    const int tid = threadIdx.x;
    const uint32_t smem_base = smem_u32(smem);
    const uint32_t fbar0 = smem_base + (uint32_t)OFF_BAR * 4u;        // full[s]
    const uint32_t ebar0 = fbar0 + 8u * NSLOT;                        // empty[s]

    // Zero data region once (guards stay zero; plane bytes overwritten by TMA).
    {
        float4* d = (float4*)smem;
        const float4 z = make_float4(0.f, 0.f, 0.f, 0.f);
        for (int i = tid; i < SM_DATA / 4; i += THREADS) d[i] = z;
    }
    if (tid == 0) {
        for (int s = 0; s < NSLOT; s++) {
            mbar_init(fbar0 + 8u * s, 1);
            mbar_init(ebar0 + 8u * s, NCW);
        }
    }
    __syncthreads();   // the only full-CTA barrier (startup)

    // ================= producer warp (whole warp) =================
    // Builds q + term tables for each tile BEFORE issuing its plane-0 TMA;
    // consumers see them via the full[plane0] acquire. Table double-buffer
    // reuse is safe: tab[ptq&1] is rewritten only after empty[slot] proves
    // all consumers are past tile ptq-1 plane 6 (reading the other buffer).
    if (tid >= NCW * 32) {
        const int lane = tid & 31;
        asm volatile("fence.proxy.async.shared::cta;" ::: "memory");
        int pnk = 0, ptq = 0, curt = 0;
        for (int p = 0;; p++) {
            int s = p % NSLOT;
            if (lane == 0 && p >= NSLOT)
                mbar_wait(ebar0 + 8u * s, ((p - NSLOT) / NSLOT) & 1);
            __syncwarp();                       // order empty-wait before table writes
            if (pnk == 0) {                     // warp-uniform
                int t = 0;
                if (lane == 0) {
                    t = atomicAdd(&g_tile_ctr, 1);
                    t = (t < NTILES) ? t : -1;
                    q[ptq & 3] = t;
                }
                t = __shfl_sync(0xffffffffu, t, 0);
                curt = t;
                if (curt >= 0) {
                    int co = curt % C_OUT, c0 = co * NK;
                    float4* tbp = tab + (ptq & 1) * 44;
                    float*  wbp = wid + (ptq & 1) * 12;
                    #pragma unroll
                    for (int pass = 0; pass < 2; pass++) {
                        int tt = lane + pass * 32;
                        if (tt < 44) {
                            int nk = tt >> 2, g = tt & 3, c = c0 + nk;
                            float4 e;
                            e.x = __int_as_float(pad_hv[c*8 + g]);
                            e.y = w1[g*C_IN + c];
                            e.z = __int_as_float(pad_hv[c*8 + 4 + g]);
                            e.w = w2[g*C_IN + c];
                            tbp[tt] = e;
                        }
                    }
                    if (lane < NK) {
                        float sw = 0.f;
                        #pragma unroll
                        for (int g = 0; g < 4; g++)
                            if (idx_identit[co*4 + g] - c0 == lane) sw += w3[g*C_OUT + co];
                        wbp[lane] = sw;
                    }
                }
                __syncwarp();                   // tables visible to lane0 before arrive
            }
            if (lane == 0) {
                uint32_t bar = fbar0 + 8u * s;
                if (curt < 0) {   // sentinel: flip full[s]; consumers see q=-1 and exit
                    asm volatile("mbarrier.arrive.shared.b64 _, [%0];" :: "r"(bar) : "memory");
                } else {
                    uint32_t dst = smem_base + (uint32_t)(GUARD + s * SLOT_STRIDE) * 4u;
                    const float* src = x + (size_t)((curt / C_OUT) * C_IN + (curt % C_OUT) * NK + pnk) * PLANE;
                    asm volatile("mbarrier.arrive.expect_tx.shared.b64 _, [%0], %1;"
                                 :: "r"(bar), "r"((uint32_t)PLANE_BYTES) : "memory");
                    asm volatile("cp.async.bulk.shared::cta.global.mbarrier::complete_tx::bytes "
                                 "[%0], [%1], %2, [%3];"
                                 :: "r"(dst), "l"(src), "r"((uint32_t)PLANE_BYTES), "r"(bar) : "memory");
                }
            }
            if (curt < 0) break;
            if (++pnk == NK) { pnk = 0; ptq++; }
        }
        return;
    }

    // ================= compute warps: pure wait -> accumulate -> arrive =================
    // h mapping (scalar, row-pure): 64 threads per row chunk, 7 chunks, k = 0..7.
    const int lh   = tid & 63;            // 0..63 (active < 56)
    const int h0h  = tid >> 6;            // 0..6
    const int colh = lh + EP;
    const int rb0h = (h0h + EP) * HIN;
    const bool act_h = (lh < WOUT);
    // v/id mapping (2-wide float2, row-pure): 1 warp per row chunk, 14 chunks, k = 0..3.
    const int l2   = tid & 31;            // 0..31 (active < 28)
    const int h0v  = tid >> 5;            // 0..13
    const int col0 = 2*l2 + EP;           // even -> LDS.64 aligned
    const int vrow0 = h0v + EP;
    const int rb0v = vrow0 * HIN;
    const bool act_v = (l2 < 28);
    const bool lane0 = (l2 == 0);

    int p = 0, tq = 0;
    for (;;) {
        int s = p % NSLOT;
        mbar_wait(fbar0 + 8u * s, (p / NSLOT) & 1);   // plane 0 ready; q + tables visible
        const int t = q[tq & 3];
        if (t < 0) break;
        const int co = t % C_OUT, b = t / C_OUT;

        const float4* tb = tab + (tq & 1) * 44;
        const float*  wb = wid + (tq & 1) * 12;

        float  acc_h[8] = {0.f,0.f,0.f,0.f,0.f,0.f,0.f,0.f};
        float2 acc_v[4] = {{0.f,0.f},{0.f,0.f},{0.f,0.f},{0.f,0.f}};
        float2 acc_i[4] = {{0.f,0.f},{0.f,0.f},{0.f,0.f},{0.f,0.f}};

        for (int nk = 0; nk < NK; nk++) {
            s = p % NSLOT;
            if (nk) mbar_wait(fbar0 + 8u * s, (p / NSLOT) & 1);
            const float* base = smem + GUARD + s * SLOT_STRIDE;
            const float* bh = base + rb0h;
            const float* bv = base + col0;

            #pragma unroll
            for (int g = 0; g < 4; g++) {
                float4 e = tb[nk*4 + g];
                int   sh = __float_as_int(e.x);
                float wh = e.y;
                int   sv = __float_as_int(e.z);
                float wv = e.w;

                // --- horizontal (scalar mapping): weight zeroed when OOB
                int iw = colh + sh;
                float wt = ((unsigned)iw < (unsigned)HIN) ? wh : 0.0f;
                const float* ph = bh + iw;
                #pragma unroll
                for (int k = 0; k < 8; k++)
                    acc_h[k] = fmaf(ph[k*RSTEP_H], wt, acc_h[k]);

                // --- vertical (float2 mapping): OOB rows hit zero guards
                const float* pv = bv + (vrow0 + sv) * HIN;
                #pragma unroll
                for (int k = 0; k < 4; k++) {
                    float2 a = *(const float2*)(pv + k*RSTEP_V);
                    acc_v[k].x = fmaf(a.x, wv, acc_v[k].x);
                    acc_v[k].y = fmaf(a.y, wv, acc_v[k].y);
                }
            }

            float wi = wb[nk];
            if (wi != 0.0f) {      // warp-uniform branch
                const float* pi = base + rb0v + col0;
                #pragma unroll
                for (int k = 0; k < 4; k++) {
                    float2 a = *(const float2*)(pi + k*RSTEP_V);
                    acc_i[k].x = fmaf(a.x, wi, acc_i[k].x);
                    acc_i[k].y = fmaf(a.y, wi, acc_i[k].y);
                }
            }

            // Warp done with slot s. Acc register deps force all this plane's
            // LDS->FFMA chains to complete before the arrive issues, so the
            // producer can never overwrite data still being read.
            if (lane0) {
                asm volatile("mbarrier.arrive.release.cta.shared::cta.b64 _, [%0];"
                    :: "r"(ebar0 + 8u * s),
                       "f"(acc_h[0]), "f"(acc_h[1]), "f"(acc_h[2]), "f"(acc_h[3]),
                       "f"(acc_h[4]), "f"(acc_h[5]), "f"(acc_h[6]), "f"(acc_h[7]),
                       "f"(acc_v[0].x), "f"(acc_v[1].y), "f"(acc_v[2].x), "f"(acc_v[3].y),
                       "f"(acc_i[0].x), "f"(acc_i[1].y), "f"(acc_i[2].x), "f"(acc_i[3].y)
                    : "memory");
            }
            p++;
        }

        // Write outputs.
        float* oh = out;
        float* ov = out + OUT_PLANE;
        float* oi = out + 2*OUT_PLANE;
        const size_t tbase = ((size_t)(b * C_OUT + co)) * NPIX;
        if (act_h) {
            const size_t ob = tbase + (size_t)h0h * WOUT + lh;
            #pragma unroll
            for (int k = 0; k < 8; k++)
                oh[ob + (size_t)(KROWS_H * k) * WOUT] = acc_h[k];
        }
        if (act_v) {
            const size_t ob = tbase + (size_t)h0v * WOUT + 2*l2;
            #pragma unroll
            for (int k = 0; k < 4; k++) {
                const size_t o1 = ob + (size_t)(KROWS_V * k) * WOUT;
                *(float2*)(ov + o1) = acc_v[k];
                *(float2*)(oi + o1) = acc_i[k];
            }
        }
        tq++;
    }
}

extern "C" void kernel_launch(void* const* d_in, const int* in_sizes, int n_in,
                              void* d_out, int out_size)
{
    const float* x           = (const float*)d_in[0];
    const float* w1          = (const float*)d_in[1];
    const float* w2          = (const float*)d_in[2];
    const float* w3          = (const float*)d_in[3];
    const int*   pad_hv      = (const int*)  d_in[4];
    const int*   idx_identit = (const int*)  d_in[5];
    float*       out         = (float*)d_out;

    cudaFuncSetAttribute(addshift_kernel,
                         cudaFuncAttributeMaxDynamicSharedMemorySize, SMEM_BYTES);

    reset_kernel<<<1, 32>>>();
    addshift_kernel<<<NCTA, THREADS, SMEM_BYTES>>>(x, w1, w2, w3, pad_hv,
                                                   idx_identit, out);
}

// round 17
// speedup vs baseline: 1.1284x; 1.0054x over previous
#include <cuda_runtime.h>
#include <cstdint>

// Problem constants (fixed by the reference).
#define C_OUT   96
#define NK      11
#define C_IN    1056
#define GB      8
#define NTILES  (C_OUT*GB)         // 768 tiles, one per (b, c_out)
#define HOUT    56
#define WOUT    56
#define HIN     60
#define EP      2
#define PLANE   3600
#define PLANE_BYTES 14400
#define NPIX    3136
#define NCW     14                 // compute warps per CTA
#define THREADS (NCW*32 + 32)      // 480: 14 compute warps + 1 producer warp
#define NCTA    296                // 2 CTAs per SM
#define OUT_PLANE ((size_t)GB*C_OUT*NPIX)

// h mapping: 64 threads (2 warps) per row chunk (7 chunks), h = h0h + 7k, k = 0..7
#define KROWS_H 7
#define RSTEP_H (KROWS_H*HIN)      // 420
// v/id mapping: 1 warp per row chunk (14 chunks, 28 active lanes x 2 w), h = h0v + 14k, k = 0..3
#define KROWS_V 14
#define RSTEP_V (KROWS_V*HIN)      // 840

// 5-slot plane ring with shared inter-slot zero guards -> ~111 KB smem,
// 2 CTAs per SM. All OOB offsets stay within [-1618, +4747] of a plane
// start; 1620-float guards (shared between adjacent slots) absorb them.
#define NSLOT       5
#define GUARD       1620
#define SLOT_STRIDE (PLANE + GUARD)                 // 5220
#define SM_DATA     (NSLOT*SLOT_STRIDE + GUARD)     // 27720 floats
#define OFF_TAB     SM_DATA                          // 2 x 44 float4 (double buffer)
#define OFF_WID     (OFF_TAB + 352)                  // 2 x 12 floats
#define OFF_Q       (OFF_WID + 24)                   // 4 ints (tile queue)
#define OFF_BAR     (OFF_Q + 4)                      // 5 full + 5 empty u64
#define SMEM_FLOATS (OFF_BAR + 20)
#define SMEM_BYTES  (SMEM_FLOATS * 4)                // ~111 KB

__device__ int g_tile_ctr;
__global__ void reset_kernel() { g_tile_ctr = 0; }

__device__ __forceinline__ uint32_t smem_u32(const void* p) {
    uint32_t a;
    asm("{ .reg .u64 t; cvta.to.shared.u64 t, %1; cvt.u32.u64 %0, t; }"
        : "=r"(a) : "l"(p));
    return a;
}
__device__ __forceinline__ void mbar_init(uint32_t mbar, uint32_t cnt) {
    asm volatile("mbarrier.init.shared.b64 [%0], %1;" :: "r"(mbar), "r"(cnt) : "memory");
}
__device__ __forceinline__ void mbar_wait(uint32_t mbar, int parity) {
    asm volatile(
        "{\n\t.reg .pred P;\n"
        "W_%=:\n\t"
        "mbarrier.try_wait.parity.acquire.cta.shared::cta.b64 P, [%0], %1, 0x989680;\n\t"
        "@P bra D_%=;\n\t"
        "bra W_%=;\n"
        "D_%=:\n\t}"
        :: "r"(mbar), "r"(parity) : "memory");
}

__global__ __launch_bounds__(THREADS, 2)
void addshift_kernel(const float* __restrict__ x,
                     const float* __restrict__ w1,
                     const float* __restrict__ w2,
                     const float* __restrict__ w3,
                     const int*   __restrict__ pad_hv,
                     const int*   __restrict__ idx_identit,
                     float* __restrict__ out)
{
    extern __shared__ float smem[];
    float4* tab = (float4*)(smem + OFF_TAB);   // [2][44]
    float*  wid = smem + OFF_WID;              // [2][12]
    int*    q   = (int*)(smem + OFF_Q);

    const int tid = threadIdx.x;
    const uint32_t smem_base = smem_u32(smem);
    const uint32_t fbar0 = smem_base + (uint32_t)OFF_BAR * 4u;        // full[s]
    const uint32_t ebar0 = fbar0 + 8u * NSLOT;                        // empty[s]

    // Zero data region once (guards stay zero; plane bytes overwritten by TMA).
    {
        float4* d = (float4*)smem;
        const float4 z = make_float4(0.f, 0.f, 0.f, 0.f);
        for (int i = tid; i < SM_DATA / 4; i += THREADS) d[i] = z;
    }
    if (tid == 0) {
        for (int s = 0; s < NSLOT; s++) {
            mbar_init(fbar0 + 8u * s, 1);
            mbar_init(ebar0 + 8u * s, NCW);
        }
    }
    __syncthreads();   // the only full-CTA barrier (startup)

    // ================= producer warp (whole warp) =================
    // Builds q + term tables for each tile BEFORE issuing its plane-0 TMA;
    // consumers see them via the full[plane0] acquire. Table double-buffer
    // reuse is safe: tab[ptq&1] is rewritten only after empty[slot] proves
    // all consumers are past tile ptq-1 plane 6 (reading the other buffer).
    if (tid >= NCW * 32) {
        const int lane = tid & 31;
        asm volatile("fence.proxy.async.shared::cta;" ::: "memory");
        int pnk = 0, ptq = 0, curt = 0;
        for (int p = 0;; p++) {
            int s = p % NSLOT;
            if (lane == 0 && p >= NSLOT)
                mbar_wait(ebar0 + 8u * s, ((p - NSLOT) / NSLOT) & 1);
            __syncwarp();                       // order empty-wait before table writes
            if (pnk == 0) {                     // warp-uniform
                int t = 0;
                if (lane == 0) {
                    t = atomicAdd(&g_tile_ctr, 1);
                    t = (t < NTILES) ? t : -1;
                    q[ptq & 3] = t;
                }
                t = __shfl_sync(0xffffffffu, t, 0);
                curt = t;
                if (curt >= 0) {
                    int co = curt % C_OUT, c0 = co * NK;
                    float4* tbp = tab + (ptq & 1) * 44;
                    float*  wbp = wid + (ptq & 1) * 12;
                    #pragma unroll
                    for (int pass = 0; pass < 2; pass++) {
                        int tt = lane + pass * 32;
                        if (tt < 44) {
                            int nk = tt >> 2, g = tt & 3, c = c0 + nk;
                            float4 e;
                            e.x = __int_as_float(pad_hv[c*8 + g]);
                            e.y = w1[g*C_IN + c];
                            e.z = __int_as_float(pad_hv[c*8 + 4 + g]);
                            e.w = w2[g*C_IN + c];
                            tbp[tt] = e;
                        }
                    }
                    if (lane < NK) {
                        float sw = 0.f;
                        #pragma unroll
                        for (int g = 0; g < 4; g++)
                            if (idx_identit[co*4 + g] - c0 == lane) sw += w3[g*C_OUT + co];
                        wbp[lane] = sw;
                    }
                }
                __syncwarp();                   // tables visible to lane0 before arrive
            }
            if (lane == 0) {
                uint32_t bar = fbar0 + 8u * s;
                if (curt < 0) {   // sentinel: flip full[s]; consumers see q=-1 and exit
                    asm volatile("mbarrier.arrive.shared.b64 _, [%0];" :: "r"(bar) : "memory");
                } else {
                    uint32_t dst = smem_base + (uint32_t)(GUARD + s * SLOT_STRIDE) * 4u;
                    const float* src = x + (size_t)((curt / C_OUT) * C_IN + (curt % C_OUT) * NK + pnk) * PLANE;
                    asm volatile("mbarrier.arrive.expect_tx.shared.b64 _, [%0], %1;"
                                 :: "r"(bar), "r"((uint32_t)PLANE_BYTES) : "memory");
                    asm volatile("cp.async.bulk.shared::cta.global.mbarrier::complete_tx::bytes "
                                 "[%0], [%1], %2, [%3];"
                                 :: "r"(dst), "l"(src), "r"((uint32_t)PLANE_BYTES), "r"(bar) : "memory");
                }
            }
            if (curt < 0) break;
            if (++pnk == NK) { pnk = 0; ptq++; }
        }
        return;
    }

    // ================= compute warps: pure wait -> accumulate -> arrive =================
    // h mapping (scalar, row-pure): 64 threads per row chunk, 7 chunks, k = 0..7.
    const int lh   = tid & 63;            // 0..63 (active < 56)
    const int h0h  = tid >> 6;            // 0..6
    const int colh = lh + EP;
    const int rb0h = (h0h + EP) * HIN;
    const bool act_h = (lh < WOUT);
    // v/id mapping (2-wide float2, row-pure): 1 warp per row chunk, 14 chunks, k = 0..3.
    const int l2   = tid & 31;            // 0..31 (active < 28)
    const int h0v  = tid >> 5;            // 0..13
    const int col0 = 2*l2 + EP;           // even -> LDS.64 aligned
    const int vrow0 = h0v + EP;
    const int rb0v = vrow0 * HIN;
    const bool act_v = (l2 < 28);
    const bool lane0 = (l2 == 0);

    int p = 0, tq = 0;
    for (;;) {
        int s = p % NSLOT;
        mbar_wait(fbar0 + 8u * s, (p / NSLOT) & 1);   // plane 0 ready; q + tables visible
        const int t = q[tq & 3];
        if (t < 0) break;
        const int co = t % C_OUT, b = t / C_OUT;

        const float4* tb = tab + (tq & 1) * 44;
        const float*  wb = wid + (tq & 1) * 12;

        float  acc_h[8] = {0.f,0.f,0.f,0.f,0.f,0.f,0.f,0.f};
        float2 acc_v[4] = {{0.f,0.f},{0.f,0.f},{0.f,0.f},{0.f,0.f}};
        float2 acc_i[4] = {{0.f,0.f},{0.f,0.f},{0.f,0.f},{0.f,0.f}};

        for (int nk = 0; nk < NK; nk++) {
            s = p % NSLOT;
            if (nk) mbar_wait(fbar0 + 8u * s, (p / NSLOT) & 1);
            const float* base = smem + GUARD + s * SLOT_STRIDE;
            const float* bh = base + rb0h;
            const float* bv = base + col0;

            #pragma unroll
            for (int g = 0; g < 4; g++) {
                float4 e = tb[nk*4 + g];
                int   sh = __float_as_int(e.x);
                float wh = e.y;
                int   sv = __float_as_int(e.z);
                float wv = e.w;

                // --- horizontal (scalar mapping): weight zeroed when OOB
                int iw = colh + sh;
                float wt = ((unsigned)iw < (unsigned)HIN) ? wh : 0.0f;
                const float* ph = bh + iw;
                #pragma unroll
                for (int k = 0; k < 8; k++)
                    acc_h[k] = fmaf(ph[k*RSTEP_H], wt, acc_h[k]);

                // --- vertical (float2 mapping): OOB rows hit zero guards
                const float* pv = bv + (vrow0 + sv) * HIN;
                #pragma unroll
                for (int k = 0; k < 4; k++) {
                    float2 a = *(const float2*)(pv + k*RSTEP_V);
                    acc_v[k].x = fmaf(a.x, wv, acc_v[k].x);
                    acc_v[k].y = fmaf(a.y, wv, acc_v[k].y);
                }
            }

            float wi = wb[nk];
            if (wi != 0.0f) {      // warp-uniform branch
                const float* pi = base + rb0v + col0;
                #pragma unroll
                for (int k = 0; k < 4; k++) {
                    float2 a = *(const float2*)(pi + k*RSTEP_V);
                    acc_i[k].x = fmaf(a.x, wi, acc_i[k].x);
                    acc_i[k].y = fmaf(a.y, wi, acc_i[k].y);
                }
            }

            // Warp done with slot s. Acc register deps force all this plane's
            // LDS->FFMA chains to complete before the arrive issues, so the
            // producer can never overwrite data still being read.
            if (lane0) {
                asm volatile("mbarrier.arrive.release.cta.shared::cta.b64 _, [%0];"
                    :: "r"(ebar0 + 8u * s),
                       "f"(acc_h[0]), "f"(acc_h[1]), "f"(acc_h[2]), "f"(acc_h[3]),
                       "f"(acc_h[4]), "f"(acc_h[5]), "f"(acc_h[6]), "f"(acc_h[7]),
                       "f"(acc_v[0].x), "f"(acc_v[1].y), "f"(acc_v[2].x), "f"(acc_v[3].y),
                       "f"(acc_i[0].x), "f"(acc_i[1].y), "f"(acc_i[2].x), "f"(acc_i[3].y)
                    : "memory");
            }
            p++;
        }

        // Write outputs.
        float* oh = out;
        float* ov = out + OUT_PLANE;
        float* oi = out + 2*OUT_PLANE;
        const size_t tbase = ((size_t)(b * C_OUT + co)) * NPIX;
        if (act_h) {
            const size_t ob = tbase + (size_t)h0h * WOUT + lh;
            #pragma unroll
            for (int k = 0; k < 8; k++)
                oh[ob + (size_t)(KROWS_H * k) * WOUT] = acc_h[k];
        }
        if (act_v) {
            const size_t ob = tbase + (size_t)h0v * WOUT + 2*l2;
            #pragma unroll
            for (int k = 0; k < 4; k++) {
                const size_t o1 = ob + (size_t)(KROWS_V * k) * WOUT;
                *(float2*)(ov + o1) = acc_v[k];
                *(float2*)(oi + o1) = acc_i[k];
            }
        }
        tq++;
    }
}

extern "C" void kernel_launch(void* const* d_in, const int* in_sizes, int n_in,
                              void* d_out, int out_size)
{
    const float* x           = (const float*)d_in[0];
    const float* w1          = (const float*)d_in[1];
    const float* w2          = (const float*)d_in[2];
    const float* w3          = (const float*)d_in[3];
    const int*   pad_hv      = (const int*)  d_in[4];
    const int*   idx_identit = (const int*)  d_in[5];
    float*       out         = (float*)d_out;

    cudaFuncSetAttribute(addshift_kernel,
                         cudaFuncAttributeMaxDynamicSharedMemorySize, SMEM_BYTES);

    reset_kernel<<<1, 32>>>();
    addshift_kernel<<<NCTA, THREADS, SMEM_BYTES>>>(x, w1, w2, w3, pad_hv,
                                                   idx_identit, out);
}